// round 15
// baseline (speedup 1.0000x reference)
#include <cuda_runtime.h>
#include <cuda_device_runtime_api.h>
#include <math_constants.h>

// ---------------------------------------------------------------------------
// IttiKochSaliency, x[8,3,512,512] -> out[8,512,512]
//
// 4 PDL-chained launches (R12 champion structure, k_comb folded into k_tail):
//  k_pyr0 : x -> L1 (256^2), separable 6-tap stride-2 reflect (+ stat/flag init)
//  k_pd1  : L1 -> L2 + diff0 + stats (768 tiles)
//  k_tail : blocks 0..23  -> per-(b,c): L2 (smem) -> L3 (smem), diff1 + stats,
//           chain i=2..6; then release g_flag[b]; the c==0 block of each batch
//           spins for all 3 channels and runs comb strips i=1 + comb_small
//           (all 152 blocks co-resident -> spin is safe);
//           blocks 24..151 -> comb strips i=0 (quad-dup float4 of sum_c s*d)
//  k_final: 7-level bilinear gather, 1 LDG.128 per level per pixel
// ---------------------------------------------------------------------------

__device__ float    g_pyr[1966080];   // L1 @0 (256^2/bc), L2 @1572864 (128^2/bc)
__device__ float    g_d[1966080];     // diff0 @0 (256^2/bc), diff1 @1572864 (128^2/bc)
__device__ float    g_d2[130944];     // diffs i=2..6 per bc (5456 each)
__device__ float4   g_q[699008];      // quad-dup combined maps per (b,i)
__device__ unsigned g_dmn[168], g_dmx[168];
__device__ float    g_tsum[168];
__device__ unsigned g_flag[8];        // per-batch tail completion counter

__constant__ int co2[7]   = {0, 524288, 655360, 688128, 696320, 698368, 698880};
__constant__ int d2off[5] = {0, 4096, 5120, 5376, 5440};

#if defined(__CUDA_ARCH__) && __CUDA_ARCH__ >= 900
#define GRID_DEP_SYNC() cudaGridDependencySynchronize()
#else
#define GRID_DEP_SYNC()
#endif

__device__ __forceinline__ int refl(int t, int n) {
    return t < 0 ? -t : (t >= n ? 2 * n - 2 - t : t);
}
__device__ __forceinline__ float calc_scale(int sidx, int i, float* mn_out) {
    float mn = __uint_as_float(g_dmn[sidx]);
    float mx = __uint_as_float(g_dmx[sidx]);
    float inv = 1.f / (mx - mn);
    int n = (16 >> i) - 1;
    float lm = (n > 0) ? (g_tsum[sidx] / (float)(n * n) - mn) * inv : 0.f;
    float om = 1.f - lm;
    *mn_out = mn;
    return om * om * inv * (1.f / 3.f);
}

#define W0 0.03125f
#define W1 0.15625f
#define W2 0.3125f

// ---------------- level 0 pyrdown: 512 -> 256 (proven) -----------------------
__global__ void __launch_bounds__(512) k_pyr0(const float* __restrict__ x) {
    constexpr int HI = 512, HO = 256;
    __shared__ float s_in[36 * 68];
    __shared__ float s_h[36 * 32];
    const int t = threadIdx.x;
    if (blockIdx.x == 0 && blockIdx.y == 0 && blockIdx.z == 0) {
        if (t < 168) { g_dmn[t] = 0xFFFFFFFFu; g_dmx[t] = 0u; g_tsum[t] = 0.f; }
        if (t >= 168 && t < 176) g_flag[t - 168] = 0u;
    }
    const int bc = blockIdx.z;
    const int ox0 = blockIdx.x * 32, oy0 = blockIdx.y * 16;
    const float* in = x + (size_t)bc * HI * HI;
    float* out = g_pyr + (size_t)bc * HO * HO;
    const int iy0 = 2 * oy0 - 2, ix0 = 2 * ox0 - 2;
    for (int idx = t; idx < 36 * 34; idx += 512) {
        int r = idx / 34, c2 = idx - r * 34;
        int gy = refl(iy0 + r, HI);
        int ix = ix0 + 2 * c2;
        float v0, v1;
        if (ix >= 0 && ix + 2 <= HI) {
            float2 p = *(const float2*)(in + gy * HI + ix);
            v0 = p.x; v1 = p.y;
        } else {
            v0 = in[gy * HI + refl(ix, HI)];
            v1 = in[gy * HI + refl(ix + 1, HI)];
        }
        s_in[r * 68 + 2 * c2] = v0;
        s_in[r * 68 + 2 * c2 + 1] = v1;
    }
    __syncthreads();
    for (int idx = t; idx < 36 * 32; idx += 512) {
        int r = idx >> 5, c = idx & 31;
        const float* p = s_in + r * 68 + 2 * c;
        s_h[idx] = W0 * (p[0] + p[5]) + W1 * (p[1] + p[4]) + W2 * (p[2] + p[3]);
    }
    __syncthreads();
    const int tx = t & 31, ty = t >> 5;
    const float* q = s_h + 2 * ty * 32 + tx;
    float acc = W0 * (q[0] + q[160]) + W1 * (q[32] + q[128]) + W2 * (q[64] + q[96]);
    out[(oy0 + ty) * HO + ox0 + tx] = acc;
}

// ---------------- pyrdown + fused diff0 (proven) ------------------------------
__global__ void __launch_bounds__(512) k_pd1() {
    constexpr int HI = 256;
    constexpr int NT = 15;
    __shared__ float s_in[36 * 68];
    __shared__ float s_h[36 * 32];
    __shared__ float sout[16 * 32];
    __shared__ unsigned s_mn, s_mx, stile[8];
    const int t = threadIdx.x;
    if (t == 0) { s_mn = 0xFFFFFFFFu; s_mx = 0u; }
    if (t < 8) stile[t] = 0u;
    GRID_DEP_SYNC();
    const int bc = blockIdx.z;
    const int ox0 = blockIdx.x * 32, oy0 = blockIdx.y * 16;
    const float* in = g_pyr + (size_t)bc * HI * HI;
    float* outp = g_pyr + 1572864 + (size_t)bc * 16384;
    const int iy0 = 2 * oy0 - 2, ix0 = 2 * ox0 - 2;
    for (int idx = t; idx < 36 * 34; idx += 512) {
        int r = idx / 34, c2 = idx - r * 34;
        int gy = refl(iy0 + r, HI);
        int ix = ix0 + 2 * c2;
        float v0, v1;
        if (ix >= 0 && ix + 2 <= HI) {
            float2 p = *(const float2*)(in + gy * HI + ix);
            v0 = p.x; v1 = p.y;
        } else {
            v0 = in[gy * HI + refl(ix, HI)];
            v1 = in[gy * HI + refl(ix + 1, HI)];
        }
        s_in[r * 68 + 2 * c2] = v0;
        s_in[r * 68 + 2 * c2 + 1] = v1;
    }
    __syncthreads();
    for (int idx = t; idx < 36 * 32; idx += 512) {
        int r = idx >> 5, c = idx & 31;
        const float* p = s_in + r * 68 + 2 * c;
        s_h[idx] = W0 * (p[0] + p[5]) + W1 * (p[1] + p[4]) + W2 * (p[2] + p[3]);
    }
    __syncthreads();
    {
        const int tx = t & 31, ty = t >> 5;
        const float* q = s_h + 2 * ty * 32 + tx;
        float acc = W0 * (q[0] + q[160]) + W1 * (q[32] + q[128]) + W2 * (q[64] + q[96]);
        outp[(oy0 + ty) * 128 + ox0 + tx] = acc;
        sout[ty * 32 + tx] = acc;
    }
    __syncthreads();
    {
        const int p = t * 4;
        const int ly = p >> 6, lx = p & 63;
        const float* fr = s_in + (ly + 2) * 68 + lx + 2;
        const float c0 = sout[(ly >> 1) * 32 + (lx >> 1)];
        const float c1 = sout[(ly >> 1) * 32 + (lx >> 1) + 1];
        float d0 = fabsf(fr[0] - c0), d1 = fabsf(fr[1] - c0);
        float d2 = fabsf(fr[2] - c1), d3 = fabsf(fr[3] - c1);
        float* gd = g_d + (size_t)bc * 65536;
        *(float4*)(gd + (2 * oy0 + ly) * 256 + 2 * ox0 + lx) = make_float4(d0, d1, d2, d3);
        float mx4 = fmaxf(fmaxf(d0, d1), fmaxf(d2, d3));
        float mn4 = fminf(fminf(d0, d1), fminf(d2, d3));
        float tm = mx4;
        tm = fmaxf(tm, __shfl_xor_sync(~0u, tm, 1, 4));
        tm = fmaxf(tm, __shfl_xor_sync(~0u, tm, 2, 4));
        if ((t & 3) == 0)
            atomicMax(&stile[(ly >> 4) * 4 + (lx >> 4)], __float_as_uint(tm));
        for (int o = 16; o; o >>= 1) {
            mx4 = fmaxf(mx4, __shfl_xor_sync(~0u, mx4, o));
            mn4 = fminf(mn4, __shfl_xor_sync(~0u, mn4, o));
        }
        if ((t & 31) == 0) {
            atomicMax(&s_mx, __float_as_uint(mx4));
            atomicMin(&s_mn, __float_as_uint(mn4));
        }
    }
    __syncthreads();
    const int sidx = bc * 7;
    if (t == 0) { atomicMin(&g_dmn[sidx], s_mn); atomicMax(&g_dmx[sidx], s_mx); }
    if (t < 8) {
        int gtc = 4 * blockIdx.x + (t & 3);
        int gtr = 2 * blockIdx.y + (t >> 2);
        if (gtc < NT && gtr < NT)
            atomicAdd(&g_tsum[sidx], __uint_as_float(stile[t]));
    }
}

// ---- per-channel tail stage (proven, 1024-thread stride) ---------------------
template <int LGF>
__device__ __forceinline__ void tail_stage2(int t, int bc, float* F, float* C,
                                            float* H, unsigned* t_mn,
                                            unsigned* t_mx, unsigned* t_tile) {
    constexpr int HF = 1 << LGF, HC = HF >> 1;
    constexpr int S = 6 - LGF;
    constexpr int OFF = (LGF == 6) ? 0 : (LGF == 5) ? 4096 :
                        (LGF == 4) ? 5120 : (LGF == 3) ? 5376 : 5440;
    for (int idx = t; idx < HF * HC; idx += 1024) {
        int r = idx >> (LGF - 1);
        const float* row = F + (r << LGF);
        int c0 = 2 * (idx & (HC - 1));
        H[idx] = W0 * (row[refl(c0 - 2, HF)] + row[refl(c0 + 3, HF)])
               + W1 * (row[refl(c0 - 1, HF)] + row[refl(c0 + 2, HF)])
               + W2 * (row[c0] + row[c0 + 1]);
    }
    __syncthreads();
    float* gd2 = g_d2 + bc * 5456 + OFF;
    for (int idx = t; idx < HC * HC; idx += 1024) {
        int oy = idx >> (LGF - 1), ox = idx & (HC - 1);
        int r0 = 2 * oy;
        float cv = W0 * (H[(refl(r0 - 2, HF) << (LGF - 1)) + ox] +
                         H[(refl(r0 + 3, HF) << (LGF - 1)) + ox])
                 + W1 * (H[(refl(r0 - 1, HF) << (LGF - 1)) + ox] +
                         H[(refl(r0 + 2, HF) << (LGF - 1)) + ox])
                 + W2 * (H[(r0 << (LGF - 1)) + ox] + H[((r0 + 1) << (LGF - 1)) + ox]);
        C[idx] = cv;
        int f0 = (oy << (LGF + 1)) + 2 * ox;
        float d00 = fabsf(F[f0] - cv),      d01 = fabsf(F[f0 + 1] - cv);
        float d10 = fabsf(F[f0 + HF] - cv), d11 = fabsf(F[f0 + HF + 1] - cv);
        F[f0] = d00; F[f0 + 1] = d01; F[f0 + HF] = d10; F[f0 + HF + 1] = d11;
        *(float2*)(gd2 + f0) = make_float2(d00, d01);
        *(float2*)(gd2 + f0 + HF) = make_float2(d10, d11);
        float mx4 = fmaxf(fmaxf(d00, d01), fmaxf(d10, d11));
        float mn4 = fminf(fminf(d00, d01), fminf(d10, d11));
        if (LGF >= 4) {
            float a = mx4, n2 = mn4;
            for (int o = 16; o; o >>= 1) {
                a = fmaxf(a, __shfl_xor_sync(~0u, a, o));
                n2 = fminf(n2, __shfl_xor_sync(~0u, n2, o));
            }
            if ((t & 31) == 0) {
                atomicMax(&t_mx[S], __float_as_uint(a));
                atomicMin(&t_mn[S], __float_as_uint(n2));
            }
        } else {
            atomicMax(&t_mx[S], __float_as_uint(mx4));
            atomicMin(&t_mn[S], __float_as_uint(mn4));
        }
        if (LGF == 6)
            atomicMax(&t_tile[(oy >> 3) * 4 + (ox >> 3)], __float_as_uint(mx4));
        else if (LGF == 5) {
            if (oy < 8 && ox < 8) atomicMax(&t_tile[16], __float_as_uint(mx4));
        }
    }
    __syncthreads();
}

// ---- comb strip (full-width 16-row strip for i=0,1), stride 1024 -------------
__device__ __forceinline__ void comb_strip(int t, int k, float* sm, float* scs) {
    int i, b, y0, lg;
    if (k < 128) { i = 0; b = k >> 4; y0 = (k & 15) * 16; lg = 8; }
    else { int r = k - 128; i = 1; b = r >> 3; y0 = (r & 7) * 16; lg = 7; }
    const int h = 1 << lg, S = h + 2, W = h + 1;
    float* sv = sm;
    if (t < 3) { float mn; scs[t] = calc_scale((b * 3 + t) * 7 + i, i, &mn); }
    __syncthreads();
    const float* db = g_d + (i ? 1572864 : 0) + (size_t)(b * 3) * h * h;
    for (int idx = t; idx < 17 * W; idx += 1024) {
        int yy = idx / W, xx = idx - yy * W;
        int gx = min(xx, h - 1), gy = min(y0 + yy, h - 1);
        const float* p = db + gy * h + gx;
        sv[yy * S + xx] = scs[0] * p[0] + scs[1] * p[h * h] + scs[2] * p[2 * h * h];
    }
    __syncthreads();
    for (int idx = t; idx < (h << 4); idx += 1024) {
        int oy = idx >> lg, ox = idx & (h - 1);
        float4 q = make_float4(sv[oy * S + ox], sv[oy * S + ox + 1],
                               sv[(oy + 1) * S + ox], sv[(oy + 1) * S + ox + 1]);
        g_q[co2[i] + b * h * h + (y0 + oy) * h + ox] = q;
    }
}

// ---- comb for one (b, i>=2) level, stride 1024 --------------------------------
__device__ __forceinline__ void comb_small(int t, int k, float* sm, float* scs) {
    const int b = k / 5, i2 = k - b * 5, i = 2 + i2;
    const int h = 64 >> i2, hp = h + 1, S = h + 2;
    float* sv = sm;
    if (t < 3) { float mn; scs[t] = calc_scale((b * 3 + t) * 7 + i, i, &mn); }
    __syncthreads();
    const float* db = g_d2 + d2off[i2];
    for (int idx = t; idx < hp * hp; idx += 1024) {
        int yy = idx / hp, xx = idx - yy * hp;
        int gx = min(xx, h - 1), gy = min(yy, h - 1);
        int p = gy * h + gx;
        sv[yy * S + xx] = scs[0] * db[(b * 3) * 5456 + p]
                        + scs[1] * db[(b * 3 + 1) * 5456 + p]
                        + scs[2] * db[(b * 3 + 2) * 5456 + p];
    }
    __syncthreads();
    for (int idx = t; idx < h * h; idx += 1024) {
        int oy = idx / h, ox = idx - oy * h;
        float4 q = make_float4(sv[oy * S + ox], sv[oy * S + ox + 1],
                               sv[(oy + 1) * S + ox], sv[(oy + 1) * S + ox + 1]);
        g_q[co2[i] + b * h * h + idx] = q;
    }
}

// ---- k_tail: tail chain (0..23) + strips i=0 (24..151) + folded comb ---------
__global__ void __launch_bounds__(1024) k_tail() {
    extern __shared__ float sm[];
    __shared__ float scs[3];
    __shared__ unsigned s1mn, s1mx, s1tile[64];
    __shared__ unsigned t_mn[5], t_mx[5], t_tile[17];
    const int t = threadIdx.x, B = blockIdx.x;
    GRID_DEP_SYNC();
    if (B >= 24) { comb_strip(t, B - 24, sm, scs); return; }

    const int bc = B;
    const int b = bc / 3;
    float* F = sm;           // 16384 (L2, then diff1 in place)
    float* H = sm + 16384;   // 8192
    float* C = sm + 24576;   // 4096 (L3)
    if (t == 0) { s1mn = 0xFFFFFFFFu; s1mx = 0u; }
    if (t < 64) s1tile[t] = 0u;
    if (t < 5) { t_mn[t] = 0xFFFFFFFFu; t_mx[t] = 0u; }
    if (t < 17) t_tile[t] = 0u;
    {
        const float4* src = (const float4*)(g_pyr + 1572864 + (size_t)bc * 16384);
        float4* F4 = (float4*)F;
        for (int idx = t; idx < 4096; idx += 1024) F4[idx] = src[idx];
    }
    __syncthreads();
    for (int idx = t; idx < 8192; idx += 1024) {
        int r = idx >> 6;
        const float* row = F + (r << 7);
        int c0 = 2 * (idx & 63);
        H[idx] = W0 * (row[refl(c0 - 2, 128)] + row[refl(c0 + 3, 128)])
               + W1 * (row[refl(c0 - 1, 128)] + row[refl(c0 + 2, 128)])
               + W2 * (row[c0] + row[c0 + 1]);
    }
    __syncthreads();
    {
        float lmn = CUDART_INF_F, lmx = -CUDART_INF_F;
        float* gd1 = g_d + 1572864 + (size_t)bc * 16384;
        for (int idx = t; idx < 4096; idx += 1024) {
            int oy = idx >> 6, ox = idx & 63;
            int r0 = 2 * oy;
            float cv = W0 * (H[(refl(r0 - 2, 128) << 6) + ox] +
                             H[(refl(r0 + 3, 128) << 6) + ox])
                     + W1 * (H[(refl(r0 - 1, 128) << 6) + ox] +
                             H[(refl(r0 + 2, 128) << 6) + ox])
                     + W2 * (H[(r0 << 6) + ox] + H[((r0 + 1) << 6) + ox]);
            C[idx] = cv;
            int f0 = (oy << 8) + 2 * ox;
            float d00 = fabsf(F[f0] - cv),       d01 = fabsf(F[f0 + 1] - cv);
            float d10 = fabsf(F[f0 + 128] - cv), d11 = fabsf(F[f0 + 129] - cv);
            *(float2*)(gd1 + f0) = make_float2(d00, d01);
            *(float2*)(gd1 + f0 + 128) = make_float2(d10, d11);
            float mx4 = fmaxf(fmaxf(d00, d01), fmaxf(d10, d11));
            float mn4 = fminf(fminf(d00, d01), fminf(d10, d11));
            atomicMax(&s1tile[(oy >> 3) * 8 + (ox >> 3)], __float_as_uint(mx4));
            lmx = fmaxf(lmx, mx4);
            lmn = fminf(lmn, mn4);
        }
        for (int o = 16; o; o >>= 1) {
            lmx = fmaxf(lmx, __shfl_xor_sync(~0u, lmx, o));
            lmn = fminf(lmn, __shfl_xor_sync(~0u, lmn, o));
        }
        if ((t & 31) == 0) {
            atomicMax(&s1mx, __float_as_uint(lmx));
            atomicMin(&s1mn, __float_as_uint(lmn));
        }
    }
    __syncthreads();
    if (t == 0) {
        float ts = 0.f;
        for (int k = 0; k < 64; k++) {
            int ty = k >> 3, tx = k & 7;
            if (tx < 7 && ty < 7) ts += __uint_as_float(s1tile[k]);
        }
        const int sidx = bc * 7 + 1;
        g_dmn[sidx] = s1mn;
        g_dmx[sidx] = s1mx;
        g_tsum[sidx] = ts;
    }
    __syncthreads();
    float* A0 = C;
    float* A1 = F;
    float* HH = F + 8192;
    tail_stage2<6>(t, bc, A0, A1, HH, t_mn, t_mx, t_tile);
    tail_stage2<5>(t, bc, A1, A0, HH, t_mn, t_mx, t_tile);
    tail_stage2<4>(t, bc, A0, A1, HH, t_mn, t_mx, t_tile);
    tail_stage2<3>(t, bc, A1, A0, HH, t_mn, t_mx, t_tile);
    tail_stage2<2>(t, bc, A0, A1, HH, t_mn, t_mx, t_tile);
    if (t < 5) {
        const int s = t, I = s + 2, sidx = bc * 7 + I;
        float ts = 0.f;
        if (s == 0) {
            for (int k = 0; k < 3; k++)
                for (int j = 0; j < 3; j++) ts += __uint_as_float(t_tile[k * 4 + j]);
        } else if (s == 1) ts = __uint_as_float(t_tile[16]);
        g_dmn[sidx] = t_mn[s];
        g_dmx[sidx] = t_mx[s];
        g_tsum[sidx] = ts;
    }
    __syncthreads();
    // ---- release: this channel's diff1/g_d2/stats are all globally visible ----
    if (t == 0) { __threadfence(); atomicAdd(&g_flag[b], 1u); }
    if (bc - b * 3 != 0) return;
    // ---- c==0 block: wait for all 3 channels, then comb i=1 strips + small ----
    if (t == 0) {
        while (((volatile unsigned*)g_flag)[b] < 3u) __nanosleep(32);
        __threadfence();
    }
    __syncthreads();
    for (int s = 0; s < 8; s++) { comb_strip(t, 128 + b * 8 + s, sm, scs); __syncthreads(); }
    for (int j = 0; j < 5; j++) { comb_small(t, b * 5 + j, sm, scs); __syncthreads(); }
}

// ---- fused final gather: 2 rows per block (proven) ----------------------------
__global__ void __launch_bounds__(1024) k_final(float* __restrict__ out) {
    __shared__ int sr0[2][7];
    __shared__ float swy[2][7], sob;
    const int t = threadIdx.x;
    const int b = blockIdx.x >> 8;
    const int yp = blockIdx.x & 255;
    GRID_DEP_SYNC();
    if (t < 32) {
        float v = 0.f;
        if (t < 21) {
            int c = t / 7, ii = t - c * 7;
            float mn;
            float sc = calc_scale((b * 3 + c) * 7 + ii, ii, &mn);
            v = -mn * sc;
        }
        for (int o = 16; o; o >>= 1) v += __shfl_xor_sync(~0u, v, o);
        if (t == 0) sob = v;
    }
    if (t >= 64 && t < 78) {
        int k = t - 64;
        int r = k / 7, ii = k - r * 7;
        int hh = 256 >> ii;
        int yy = 2 * yp + r;
        float fy = fminf(fmaxf((yy + 0.5f) * (float)hh * (1.f / 512.f) - 0.5f, 0.f),
                         (float)(hh - 1));
        int y0 = (int)fy;
        swy[r][ii] = fy - (float)y0;
        sr0[r][ii] = y0 * hh;
    }
    __syncthreads();
    const int r = t >> 9;
    const int x = t & 511;
    const int y = 2 * yp + r;
    float acc = 0.f;
#pragma unroll
    for (int i = 0; i < 7; i++) {
        const int hh = 256 >> i;
        float fx = fminf(fmaxf((x + 0.5f) * (float)hh * (1.f / 512.f) - 0.5f, 0.f),
                         (float)(hh - 1));
        int x0 = (int)fx;
        float wx = fx - (float)x0;
        float4 p = g_q[co2[i] + (size_t)b * hh * hh + sr0[r][i] + x0];
        float v0 = fmaf(wx, p.y - p.x, p.x);
        float v1 = fmaf(wx, p.w - p.z, p.z);
        acc += fmaf(swy[r][i], v1 - v0, v0);
    }
    out[((size_t)b << 18) + y * 512 + x] = acc + sob;
}

// ---- host: PDL launcher with plain-launch fallback ----------------------------
static void pdl_launch(const void* fn, dim3 grid, dim3 block, size_t smem,
                       void** args) {
    cudaLaunchConfig_t cfg = {};
    cfg.gridDim = grid;
    cfg.blockDim = block;
    cfg.dynamicSmemBytes = smem;
    cfg.stream = 0;
    cudaLaunchAttribute at[1];
    at[0].id = cudaLaunchAttributeProgrammaticStreamSerialization;
    at[0].val.programmaticStreamSerializationAllowed = 1;
    cfg.attrs = at;
    cfg.numAttrs = 1;
    if (cudaLaunchKernelExC(&cfg, fn, args) != cudaSuccess) {
        cudaLaunchKernel(fn, grid, block, args, smem, 0);
    }
}

extern "C" void kernel_launch(void* const* d_in, const int* in_sizes, int n_in,
                              void* d_out, int out_size) {
    const float* x = (const float*)d_in[0];
    float* out = (float*)d_out;

    cudaFuncSetAttribute(k_tail, cudaFuncAttributeMaxDynamicSharedMemorySize, 114688);

    k_pyr0<<<dim3(8, 16, 24), 512>>>(x);
    pdl_launch((const void*)k_pd1, dim3(4, 8, 24), dim3(512), 0, nullptr);
    pdl_launch((const void*)k_tail, dim3(152), dim3(1024), 114688, nullptr);
    void* fargs[] = {&out};
    pdl_launch((const void*)k_final, dim3(2048), dim3(1024), 0, fargs);
}

// round 16
// speedup vs baseline: 1.3166x; 1.3166x over previous
#include <cuda_runtime.h>
#include <cuda_device_runtime_api.h>
#include <math_constants.h>

// ---------------------------------------------------------------------------
// IttiKochSaliency, x[8,3,512,512] -> out[8,512,512]
//
// 4 PDL-chained launches (R12 structure; k_comb folded into k_tail with the
// comb work DISTRIBUTED over the 104 early-finishing strip blocks):
//  k_pyr0 : x -> L1 (256^2), separable 6-tap stride-2 reflect (+ stat/flag init)
//  k_pd1  : L1 -> L2 + diff0 + stats (768 tiles)
//  k_tail : blocks 0..23  -> per-(b,c) tail chain (L2->L3, diff1, i=2..6),
//           then release g_flag[b];
//           blocks 24..151 -> comb strip i=0, then blocks 24..127 each spin on
//           their batch flag and run ONE comb item (i=1 strip or comb_small).
//           All 152 blocks co-resident (2 blocks/SM) -> spin is deadlock-free.
//  k_final: 7-level bilinear gather, 1 LDG.128 per level per pixel
// ---------------------------------------------------------------------------

__device__ float    g_pyr[1966080];   // L1 @0 (256^2/bc), L2 @1572864 (128^2/bc)
__device__ float    g_d[1966080];     // diff0 @0 (256^2/bc), diff1 @1572864 (128^2/bc)
__device__ float    g_d2[130944];     // diffs i=2..6 per bc (5456 each)
__device__ float4   g_q[699008];      // quad-dup combined maps per (b,i)
__device__ unsigned g_dmn[168], g_dmx[168];
__device__ float    g_tsum[168];
__device__ unsigned g_flag[8];        // per-batch tail completion counter

__constant__ int co2[7]   = {0, 524288, 655360, 688128, 696320, 698368, 698880};
__constant__ int d2off[5] = {0, 4096, 5120, 5376, 5440};

#if defined(__CUDA_ARCH__) && __CUDA_ARCH__ >= 900
#define GRID_DEP_SYNC() cudaGridDependencySynchronize()
#else
#define GRID_DEP_SYNC()
#endif

__device__ __forceinline__ int refl(int t, int n) {
    return t < 0 ? -t : (t >= n ? 2 * n - 2 - t : t);
}
__device__ __forceinline__ float calc_scale(int sidx, int i, float* mn_out) {
    float mn = __uint_as_float(g_dmn[sidx]);
    float mx = __uint_as_float(g_dmx[sidx]);
    float inv = 1.f / (mx - mn);
    int n = (16 >> i) - 1;
    float lm = (n > 0) ? (g_tsum[sidx] / (float)(n * n) - mn) * inv : 0.f;
    float om = 1.f - lm;
    *mn_out = mn;
    return om * om * inv * (1.f / 3.f);
}

#define W0 0.03125f
#define W1 0.15625f
#define W2 0.3125f

// ---------------- level 0 pyrdown: 512 -> 256 (proven) -----------------------
__global__ void __launch_bounds__(512) k_pyr0(const float* __restrict__ x) {
    constexpr int HI = 512, HO = 256;
    __shared__ float s_in[36 * 68];
    __shared__ float s_h[36 * 32];
    const int t = threadIdx.x;
    if (blockIdx.x == 0 && blockIdx.y == 0 && blockIdx.z == 0) {
        if (t < 168) { g_dmn[t] = 0xFFFFFFFFu; g_dmx[t] = 0u; g_tsum[t] = 0.f; }
        if (t >= 168 && t < 176) g_flag[t - 168] = 0u;
    }
    const int bc = blockIdx.z;
    const int ox0 = blockIdx.x * 32, oy0 = blockIdx.y * 16;
    const float* in = x + (size_t)bc * HI * HI;
    float* out = g_pyr + (size_t)bc * HO * HO;
    const int iy0 = 2 * oy0 - 2, ix0 = 2 * ox0 - 2;
    for (int idx = t; idx < 36 * 34; idx += 512) {
        int r = idx / 34, c2 = idx - r * 34;
        int gy = refl(iy0 + r, HI);
        int ix = ix0 + 2 * c2;
        float v0, v1;
        if (ix >= 0 && ix + 2 <= HI) {
            float2 p = *(const float2*)(in + gy * HI + ix);
            v0 = p.x; v1 = p.y;
        } else {
            v0 = in[gy * HI + refl(ix, HI)];
            v1 = in[gy * HI + refl(ix + 1, HI)];
        }
        s_in[r * 68 + 2 * c2] = v0;
        s_in[r * 68 + 2 * c2 + 1] = v1;
    }
    __syncthreads();
    for (int idx = t; idx < 36 * 32; idx += 512) {
        int r = idx >> 5, c = idx & 31;
        const float* p = s_in + r * 68 + 2 * c;
        s_h[idx] = W0 * (p[0] + p[5]) + W1 * (p[1] + p[4]) + W2 * (p[2] + p[3]);
    }
    __syncthreads();
    const int tx = t & 31, ty = t >> 5;
    const float* q = s_h + 2 * ty * 32 + tx;
    float acc = W0 * (q[0] + q[160]) + W1 * (q[32] + q[128]) + W2 * (q[64] + q[96]);
    out[(oy0 + ty) * HO + ox0 + tx] = acc;
}

// ---------------- pyrdown + fused diff0 (proven) ------------------------------
__global__ void __launch_bounds__(512) k_pd1() {
    constexpr int HI = 256;
    constexpr int NT = 15;
    __shared__ float s_in[36 * 68];
    __shared__ float s_h[36 * 32];
    __shared__ float sout[16 * 32];
    __shared__ unsigned s_mn, s_mx, stile[8];
    const int t = threadIdx.x;
    if (t == 0) { s_mn = 0xFFFFFFFFu; s_mx = 0u; }
    if (t < 8) stile[t] = 0u;
    GRID_DEP_SYNC();
    const int bc = blockIdx.z;
    const int ox0 = blockIdx.x * 32, oy0 = blockIdx.y * 16;
    const float* in = g_pyr + (size_t)bc * HI * HI;
    float* outp = g_pyr + 1572864 + (size_t)bc * 16384;
    const int iy0 = 2 * oy0 - 2, ix0 = 2 * ox0 - 2;
    for (int idx = t; idx < 36 * 34; idx += 512) {
        int r = idx / 34, c2 = idx - r * 34;
        int gy = refl(iy0 + r, HI);
        int ix = ix0 + 2 * c2;
        float v0, v1;
        if (ix >= 0 && ix + 2 <= HI) {
            float2 p = *(const float2*)(in + gy * HI + ix);
            v0 = p.x; v1 = p.y;
        } else {
            v0 = in[gy * HI + refl(ix, HI)];
            v1 = in[gy * HI + refl(ix + 1, HI)];
        }
        s_in[r * 68 + 2 * c2] = v0;
        s_in[r * 68 + 2 * c2 + 1] = v1;
    }
    __syncthreads();
    for (int idx = t; idx < 36 * 32; idx += 512) {
        int r = idx >> 5, c = idx & 31;
        const float* p = s_in + r * 68 + 2 * c;
        s_h[idx] = W0 * (p[0] + p[5]) + W1 * (p[1] + p[4]) + W2 * (p[2] + p[3]);
    }
    __syncthreads();
    {
        const int tx = t & 31, ty = t >> 5;
        const float* q = s_h + 2 * ty * 32 + tx;
        float acc = W0 * (q[0] + q[160]) + W1 * (q[32] + q[128]) + W2 * (q[64] + q[96]);
        outp[(oy0 + ty) * 128 + ox0 + tx] = acc;
        sout[ty * 32 + tx] = acc;
    }
    __syncthreads();
    {
        const int p = t * 4;
        const int ly = p >> 6, lx = p & 63;
        const float* fr = s_in + (ly + 2) * 68 + lx + 2;
        const float c0 = sout[(ly >> 1) * 32 + (lx >> 1)];
        const float c1 = sout[(ly >> 1) * 32 + (lx >> 1) + 1];
        float d0 = fabsf(fr[0] - c0), d1 = fabsf(fr[1] - c0);
        float d2 = fabsf(fr[2] - c1), d3 = fabsf(fr[3] - c1);
        float* gd = g_d + (size_t)bc * 65536;
        *(float4*)(gd + (2 * oy0 + ly) * 256 + 2 * ox0 + lx) = make_float4(d0, d1, d2, d3);
        float mx4 = fmaxf(fmaxf(d0, d1), fmaxf(d2, d3));
        float mn4 = fminf(fminf(d0, d1), fminf(d2, d3));
        float tm = mx4;
        tm = fmaxf(tm, __shfl_xor_sync(~0u, tm, 1, 4));
        tm = fmaxf(tm, __shfl_xor_sync(~0u, tm, 2, 4));
        if ((t & 3) == 0)
            atomicMax(&stile[(ly >> 4) * 4 + (lx >> 4)], __float_as_uint(tm));
        for (int o = 16; o; o >>= 1) {
            mx4 = fmaxf(mx4, __shfl_xor_sync(~0u, mx4, o));
            mn4 = fminf(mn4, __shfl_xor_sync(~0u, mn4, o));
        }
        if ((t & 31) == 0) {
            atomicMax(&s_mx, __float_as_uint(mx4));
            atomicMin(&s_mn, __float_as_uint(mn4));
        }
    }
    __syncthreads();
    const int sidx = bc * 7;
    if (t == 0) { atomicMin(&g_dmn[sidx], s_mn); atomicMax(&g_dmx[sidx], s_mx); }
    if (t < 8) {
        int gtc = 4 * blockIdx.x + (t & 3);
        int gtr = 2 * blockIdx.y + (t >> 2);
        if (gtc < NT && gtr < NT)
            atomicAdd(&g_tsum[sidx], __uint_as_float(stile[t]));
    }
}

// ---- per-channel tail stage (proven, 1024-thread stride) ---------------------
template <int LGF>
__device__ __forceinline__ void tail_stage2(int t, int bc, float* F, float* C,
                                            float* H, unsigned* t_mn,
                                            unsigned* t_mx, unsigned* t_tile) {
    constexpr int HF = 1 << LGF, HC = HF >> 1;
    constexpr int S = 6 - LGF;
    constexpr int OFF = (LGF == 6) ? 0 : (LGF == 5) ? 4096 :
                        (LGF == 4) ? 5120 : (LGF == 3) ? 5376 : 5440;
    for (int idx = t; idx < HF * HC; idx += 1024) {
        int r = idx >> (LGF - 1);
        const float* row = F + (r << LGF);
        int c0 = 2 * (idx & (HC - 1));
        H[idx] = W0 * (row[refl(c0 - 2, HF)] + row[refl(c0 + 3, HF)])
               + W1 * (row[refl(c0 - 1, HF)] + row[refl(c0 + 2, HF)])
               + W2 * (row[c0] + row[c0 + 1]);
    }
    __syncthreads();
    float* gd2 = g_d2 + bc * 5456 + OFF;
    for (int idx = t; idx < HC * HC; idx += 1024) {
        int oy = idx >> (LGF - 1), ox = idx & (HC - 1);
        int r0 = 2 * oy;
        float cv = W0 * (H[(refl(r0 - 2, HF) << (LGF - 1)) + ox] +
                         H[(refl(r0 + 3, HF) << (LGF - 1)) + ox])
                 + W1 * (H[(refl(r0 - 1, HF) << (LGF - 1)) + ox] +
                         H[(refl(r0 + 2, HF) << (LGF - 1)) + ox])
                 + W2 * (H[(r0 << (LGF - 1)) + ox] + H[((r0 + 1) << (LGF - 1)) + ox]);
        C[idx] = cv;
        int f0 = (oy << (LGF + 1)) + 2 * ox;
        float d00 = fabsf(F[f0] - cv),      d01 = fabsf(F[f0 + 1] - cv);
        float d10 = fabsf(F[f0 + HF] - cv), d11 = fabsf(F[f0 + HF + 1] - cv);
        F[f0] = d00; F[f0 + 1] = d01; F[f0 + HF] = d10; F[f0 + HF + 1] = d11;
        *(float2*)(gd2 + f0) = make_float2(d00, d01);
        *(float2*)(gd2 + f0 + HF) = make_float2(d10, d11);
        float mx4 = fmaxf(fmaxf(d00, d01), fmaxf(d10, d11));
        float mn4 = fminf(fminf(d00, d01), fminf(d10, d11));
        if (LGF >= 4) {
            float a = mx4, n2 = mn4;
            for (int o = 16; o; o >>= 1) {
                a = fmaxf(a, __shfl_xor_sync(~0u, a, o));
                n2 = fminf(n2, __shfl_xor_sync(~0u, n2, o));
            }
            if ((t & 31) == 0) {
                atomicMax(&t_mx[S], __float_as_uint(a));
                atomicMin(&t_mn[S], __float_as_uint(n2));
            }
        } else {
            atomicMax(&t_mx[S], __float_as_uint(mx4));
            atomicMin(&t_mn[S], __float_as_uint(mn4));
        }
        if (LGF == 6)
            atomicMax(&t_tile[(oy >> 3) * 4 + (ox >> 3)], __float_as_uint(mx4));
        else if (LGF == 5) {
            if (oy < 8 && ox < 8) atomicMax(&t_tile[16], __float_as_uint(mx4));
        }
    }
    __syncthreads();
}

// ---- comb strip (full-width 16-row strip for i=0,1), stride 1024 -------------
__device__ __forceinline__ void comb_strip(int t, int k, float* sm, float* scs) {
    int i, b, y0, lg;
    if (k < 128) { i = 0; b = k >> 4; y0 = (k & 15) * 16; lg = 8; }
    else { int r = k - 128; i = 1; b = r >> 3; y0 = (r & 7) * 16; lg = 7; }
    const int h = 1 << lg, S = h + 2, W = h + 1;
    float* sv = sm;
    if (t < 3) { float mn; scs[t] = calc_scale((b * 3 + t) * 7 + i, i, &mn); }
    __syncthreads();
    const float* db = g_d + (i ? 1572864 : 0) + (size_t)(b * 3) * h * h;
    for (int idx = t; idx < 17 * W; idx += 1024) {
        int yy = idx / W, xx = idx - yy * W;
        int gx = min(xx, h - 1), gy = min(y0 + yy, h - 1);
        const float* p = db + gy * h + gx;
        sv[yy * S + xx] = scs[0] * p[0] + scs[1] * p[h * h] + scs[2] * p[2 * h * h];
    }
    __syncthreads();
    for (int idx = t; idx < (h << 4); idx += 1024) {
        int oy = idx >> lg, ox = idx & (h - 1);
        float4 q = make_float4(sv[oy * S + ox], sv[oy * S + ox + 1],
                               sv[(oy + 1) * S + ox], sv[(oy + 1) * S + ox + 1]);
        g_q[co2[i] + b * h * h + (y0 + oy) * h + ox] = q;
    }
}

// ---- comb for one (b, i>=2) level, stride 1024 --------------------------------
__device__ __forceinline__ void comb_small(int t, int k, float* sm, float* scs) {
    const int b = k / 5, i2 = k - b * 5, i = 2 + i2;
    const int h = 64 >> i2, hp = h + 1, S = h + 2;
    float* sv = sm;
    if (t < 3) { float mn; scs[t] = calc_scale((b * 3 + t) * 7 + i, i, &mn); }
    __syncthreads();
    const float* db = g_d2 + d2off[i2];
    for (int idx = t; idx < hp * hp; idx += 1024) {
        int yy = idx / hp, xx = idx - yy * hp;
        int gx = min(xx, h - 1), gy = min(yy, h - 1);
        int p = gy * h + gx;
        sv[yy * S + xx] = scs[0] * db[(b * 3) * 5456 + p]
                        + scs[1] * db[(b * 3 + 1) * 5456 + p]
                        + scs[2] * db[(b * 3 + 2) * 5456 + p];
    }
    __syncthreads();
    for (int idx = t; idx < h * h; idx += 1024) {
        int oy = idx / h, ox = idx - oy * h;
        float4 q = make_float4(sv[oy * S + ox], sv[oy * S + ox + 1],
                               sv[(oy + 1) * S + ox], sv[(oy + 1) * S + ox + 1]);
        g_q[co2[i] + b * h * h + idx] = q;
    }
}

// ---- k_tail: tail chain (0..23) + strips i=0 + distributed comb (24..151) ----
__global__ void __launch_bounds__(1024) k_tail() {
    extern __shared__ float sm[];
    __shared__ float scs[3];
    __shared__ unsigned s1mn, s1mx, s1tile[64];
    __shared__ unsigned t_mn[5], t_mx[5], t_tile[17];
    const int t = threadIdx.x, B = blockIdx.x;
    GRID_DEP_SYNC();
    if (B >= 24) {
        comb_strip(t, B - 24, sm, scs);           // i=0 strip (needs only pd1)
        const int item = B - 24;                   // 0..127
        if (item < 104) {                          // one deferred comb item
            const int bwait = (item < 64) ? (item >> 3) : (item - 64) / 5;
            if (t == 0) {
                while (((volatile unsigned*)g_flag)[bwait] < 3u) __nanosleep(32);
                __threadfence();
            }
            __syncthreads();
            if (item < 64) comb_strip(t, 128 + item, sm, scs);   // i=1 strip
            else comb_small(t, item - 64, sm, scs);              // i=2..6
        }
        return;
    }

    const int bc = B;
    const int b = bc / 3;
    float* F = sm;           // 16384 (L2, then diff1 in place)
    float* H = sm + 16384;   // 8192
    float* C = sm + 24576;   // 4096 (L3)
    if (t == 0) { s1mn = 0xFFFFFFFFu; s1mx = 0u; }
    if (t < 64) s1tile[t] = 0u;
    if (t < 5) { t_mn[t] = 0xFFFFFFFFu; t_mx[t] = 0u; }
    if (t < 17) t_tile[t] = 0u;
    {
        const float4* src = (const float4*)(g_pyr + 1572864 + (size_t)bc * 16384);
        float4* F4 = (float4*)F;
        for (int idx = t; idx < 4096; idx += 1024) F4[idx] = src[idx];
    }
    __syncthreads();
    for (int idx = t; idx < 8192; idx += 1024) {
        int r = idx >> 6;
        const float* row = F + (r << 7);
        int c0 = 2 * (idx & 63);
        H[idx] = W0 * (row[refl(c0 - 2, 128)] + row[refl(c0 + 3, 128)])
               + W1 * (row[refl(c0 - 1, 128)] + row[refl(c0 + 2, 128)])
               + W2 * (row[c0] + row[c0 + 1]);
    }
    __syncthreads();
    {
        float lmn = CUDART_INF_F, lmx = -CUDART_INF_F;
        float* gd1 = g_d + 1572864 + (size_t)bc * 16384;
        for (int idx = t; idx < 4096; idx += 1024) {
            int oy = idx >> 6, ox = idx & 63;
            int r0 = 2 * oy;
            float cv = W0 * (H[(refl(r0 - 2, 128) << 6) + ox] +
                             H[(refl(r0 + 3, 128) << 6) + ox])
                     + W1 * (H[(refl(r0 - 1, 128) << 6) + ox] +
                             H[(refl(r0 + 2, 128) << 6) + ox])
                     + W2 * (H[(r0 << 6) + ox] + H[((r0 + 1) << 6) + ox]);
            C[idx] = cv;
            int f0 = (oy << 8) + 2 * ox;
            float d00 = fabsf(F[f0] - cv),       d01 = fabsf(F[f0 + 1] - cv);
            float d10 = fabsf(F[f0 + 128] - cv), d11 = fabsf(F[f0 + 129] - cv);
            *(float2*)(gd1 + f0) = make_float2(d00, d01);
            *(float2*)(gd1 + f0 + 128) = make_float2(d10, d11);
            float mx4 = fmaxf(fmaxf(d00, d01), fmaxf(d10, d11));
            float mn4 = fminf(fminf(d00, d01), fminf(d10, d11));
            atomicMax(&s1tile[(oy >> 3) * 8 + (ox >> 3)], __float_as_uint(mx4));
            lmx = fmaxf(lmx, mx4);
            lmn = fminf(lmn, mn4);
        }
        for (int o = 16; o; o >>= 1) {
            lmx = fmaxf(lmx, __shfl_xor_sync(~0u, lmx, o));
            lmn = fminf(lmn, __shfl_xor_sync(~0u, lmn, o));
        }
        if ((t & 31) == 0) {
            atomicMax(&s1mx, __float_as_uint(lmx));
            atomicMin(&s1mn, __float_as_uint(lmn));
        }
    }
    __syncthreads();
    if (t == 0) {
        float ts = 0.f;
        for (int k = 0; k < 64; k++) {
            int ty = k >> 3, tx = k & 7;
            if (tx < 7 && ty < 7) ts += __uint_as_float(s1tile[k]);
        }
        const int sidx = bc * 7 + 1;
        g_dmn[sidx] = s1mn;
        g_dmx[sidx] = s1mx;
        g_tsum[sidx] = ts;
    }
    __syncthreads();
    float* A0 = C;
    float* A1 = F;
    float* HH = F + 8192;
    tail_stage2<6>(t, bc, A0, A1, HH, t_mn, t_mx, t_tile);
    tail_stage2<5>(t, bc, A1, A0, HH, t_mn, t_mx, t_tile);
    tail_stage2<4>(t, bc, A0, A1, HH, t_mn, t_mx, t_tile);
    tail_stage2<3>(t, bc, A1, A0, HH, t_mn, t_mx, t_tile);
    tail_stage2<2>(t, bc, A0, A1, HH, t_mn, t_mx, t_tile);
    if (t < 5) {
        const int s = t, I = s + 2, sidx = bc * 7 + I;
        float ts = 0.f;
        if (s == 0) {
            for (int k = 0; k < 3; k++)
                for (int j = 0; j < 3; j++) ts += __uint_as_float(t_tile[k * 4 + j]);
        } else if (s == 1) ts = __uint_as_float(t_tile[16]);
        g_dmn[sidx] = t_mn[s];
        g_dmx[sidx] = t_mx[s];
        g_tsum[sidx] = ts;
    }
    __syncthreads();
    // release: this channel's diff1 / g_d2 / stats are globally visible
    if (t == 0) { __threadfence(); atomicAdd(&g_flag[b], 1u); }
}

// ---- fused final gather: 2 rows per block (proven) ----------------------------
__global__ void __launch_bounds__(1024) k_final(float* __restrict__ out) {
    __shared__ int sr0[2][7];
    __shared__ float swy[2][7], sob;
    const int t = threadIdx.x;
    const int b = blockIdx.x >> 8;
    const int yp = blockIdx.x & 255;
    GRID_DEP_SYNC();
    if (t < 32) {
        float v = 0.f;
        if (t < 21) {
            int c = t / 7, ii = t - c * 7;
            float mn;
            float sc = calc_scale((b * 3 + c) * 7 + ii, ii, &mn);
            v = -mn * sc;
        }
        for (int o = 16; o; o >>= 1) v += __shfl_xor_sync(~0u, v, o);
        if (t == 0) sob = v;
    }
    if (t >= 64 && t < 78) {
        int k = t - 64;
        int r = k / 7, ii = k - r * 7;
        int hh = 256 >> ii;
        int yy = 2 * yp + r;
        float fy = fminf(fmaxf((yy + 0.5f) * (float)hh * (1.f / 512.f) - 0.5f, 0.f),
                         (float)(hh - 1));
        int y0 = (int)fy;
        swy[r][ii] = fy - (float)y0;
        sr0[r][ii] = y0 * hh;
    }
    __syncthreads();
    const int r = t >> 9;
    const int x = t & 511;
    const int y = 2 * yp + r;
    float acc = 0.f;
#pragma unroll
    for (int i = 0; i < 7; i++) {
        const int hh = 256 >> i;
        float fx = fminf(fmaxf((x + 0.5f) * (float)hh * (1.f / 512.f) - 0.5f, 0.f),
                         (float)(hh - 1));
        int x0 = (int)fx;
        float wx = fx - (float)x0;
        float4 p = g_q[co2[i] + (size_t)b * hh * hh + sr0[r][i] + x0];
        float v0 = fmaf(wx, p.y - p.x, p.x);
        float v1 = fmaf(wx, p.w - p.z, p.z);
        acc += fmaf(swy[r][i], v1 - v0, v0);
    }
    out[((size_t)b << 18) + y * 512 + x] = acc + sob;
}

// ---- host: PDL launcher with plain-launch fallback ----------------------------
static void pdl_launch(const void* fn, dim3 grid, dim3 block, size_t smem,
                       void** args) {
    cudaLaunchConfig_t cfg = {};
    cfg.gridDim = grid;
    cfg.blockDim = block;
    cfg.dynamicSmemBytes = smem;
    cfg.stream = 0;
    cudaLaunchAttribute at[1];
    at[0].id = cudaLaunchAttributeProgrammaticStreamSerialization;
    at[0].val.programmaticStreamSerializationAllowed = 1;
    cfg.attrs = at;
    cfg.numAttrs = 1;
    if (cudaLaunchKernelExC(&cfg, fn, args) != cudaSuccess) {
        cudaLaunchKernel(fn, grid, block, args, smem, 0);
    }
}

extern "C" void kernel_launch(void* const* d_in, const int* in_sizes, int n_in,
                              void* d_out, int out_size) {
    const float* x = (const float*)d_in[0];
    float* out = (float*)d_out;

    cudaFuncSetAttribute(k_tail, cudaFuncAttributeMaxDynamicSharedMemorySize, 114688);

    k_pyr0<<<dim3(8, 16, 24), 512>>>(x);
    pdl_launch((const void*)k_pd1, dim3(4, 8, 24), dim3(512), 0, nullptr);
    pdl_launch((const void*)k_tail, dim3(152), dim3(1024), 114688, nullptr);
    void* fargs[] = {&out};
    pdl_launch((const void*)k_final, dim3(2048), dim3(1024), 0, fargs);
}